// round 4
// baseline (speedup 1.0000x reference)
#include <cuda_runtime.h>
#include <cstdint>

#define NN 384
#define HH 768
#define NB 144                              // grid size; <= 148 SMs -> all co-resident
#define INV_SQRT_H 0.03608439182435161f     // 1/sqrt(768)
#define INV_N      0.0026041666666666665f   // 1/384

// ---------------- scratch (device globals; no allocation allowed) ----------
__device__ float g_E [NN * NN];             // exp(att)            576 KB
__device__ float g_ET[NN * NN];             // exp(att) transposed 576 KB
__device__ float g_rinv[NN], g_cinv[NN];    // 1/rowsum(E), 1/colsum(E)
__device__ float g_a[NN], g_b[NN];          // pre-scaled typicalness factors
__device__ float g_w_hypo[NN], g_w_hyper[NN];
__device__ float g_hpart[64 * HH], g_xpart[64 * HH];
__device__ float g_hp[HH], g_xp[HH];
__device__ unsigned g_arrive;               // monotonic barrier counter (replay-safe)

// ---------------- f16x2 helpers ----------------
__device__ __forceinline__ uint32_t packh2(float a, float b) {
    // packs {a,b} into f16x2 (operand->half mapping consistent for X and Y,
    // so product pairing k<->k holds regardless of hi/lo convention)
    uint32_t d;
    asm("cvt.rn.f16x2.f32 %0, %1, %2;" : "=r"(d) : "f"(b), "f"(a));
    return d;
}
__device__ __forceinline__ uint32_t hmul2(uint32_t a, uint32_t b) {
    uint32_t d;
    asm("mul.rn.f16x2 %0, %1, %2;" : "=r"(d) : "r"(a), "r"(b));
    return d;
}
__device__ __forceinline__ uint32_t hadd2(uint32_t a, uint32_t b) {
    uint32_t d;
    asm("add.rn.f16x2 %0, %1, %2;" : "=r"(d) : "r"(a), "r"(b));
    return d;
}
__device__ __forceinline__ uint32_t htanh2(uint32_t a) {
    uint32_t d;
    asm("tanh.approx.f16x2 %0, %1;" : "=r"(d) : "r"(a));
    return d;
}
__device__ __forceinline__ float h2sum(uint32_t s) {
    float lo, hi;
    asm("{ .reg .b16 l, h;\n\t"
        "  mov.b32 {l, h}, %2;\n\t"
        "  cvt.f32.f16 %0, l;\n\t"
        "  cvt.f32.f16 %1, h; }"
        : "=f"(lo), "=f"(hi) : "r"(s));
    return lo + hi;
}

__device__ __forceinline__ float warp_sum(float v) {
    #pragma unroll
    for (int o = 16; o; o >>= 1) v += __shfl_xor_sync(0xffffffffu, v, o);
    return v;
}

// Software grid barrier. Monotonic counter -> safe across CUDA-graph replays.
__device__ __forceinline__ void grid_barrier() {
    __syncthreads();
    __threadfence();
    if (threadIdx.x == 0) {
        unsigned my = atomicAdd(&g_arrive, 1u) + 1u;
        unsigned target = ((my + NB - 1u) / NB) * NB;
        unsigned cur;
        do {
            asm volatile("ld.global.acquire.gpu.b32 %0, [%1];"
                         : "=r"(cur) : "l"(&g_arrive));
        } while ((int)(cur - target) < 0);
    }
    __syncthreads();
    __threadfence();
}

// ---------------- single fused kernel ----------------------------------------
__global__ __launch_bounds__(256) void fused_kernel(const float* __restrict__ X,
                                                    const float* __restrict__ Y,
                                                    const float* __restrict__ W,
                                                    const float* __restrict__ B,
                                                    float* __restrict__ out) {
    __shared__ uint32_t sX2[32][17];   // f16x2-packed tiles (k-pairs)
    __shared__ uint32_t sY2[32][17];

    const int tid = threadIdx.x;
    const int lane = tid & 31;
    const int wid = tid >> 5;

    // ===== Phase 0: E[n,m] = exp(invsqrt * sum_h tanh(X[n,h]*Y[m,h])) =======
    // 144 blocks = 12x12 tiles of 32x32; 16x16 threads, 2x2 micro-tile.
    // f16x2 pipeline: HMUL2 -> TANH2 (MUFU, 2 lanes/slot) -> HADD2 tree -> f32.
    {
        const int tx = tid & 15;
        const int ty = tid >> 4;
        const int bi = (blockIdx.x / 12) * 32;   // hypo rows
        const int bj = (blockIdx.x % 12) * 32;   // hyper rows
        const int lr = tid >> 3;                 // 0..31 load row
        const int lf = (tid & 7) << 2;           // float offset 0..28
        const int lh = (tid & 7) << 1;           // half2 offset 0..14

        float a00 = 0.f, a01 = 0.f, a10 = 0.f, a11 = 0.f;

        for (int k0 = 0; k0 < HH; k0 += 32) {
            float4 vx = *(const float4*)(X + (size_t)(bi + lr) * HH + k0 + lf);
            float4 vy = *(const float4*)(Y + (size_t)(bj + lr) * HH + k0 + lf);
            sX2[lr][lh]     = packh2(vx.x, vx.y);
            sX2[lr][lh + 1] = packh2(vx.z, vx.w);
            sY2[lr][lh]     = packh2(vy.x, vy.y);
            sY2[lr][lh + 1] = packh2(vy.z, vy.w);
            __syncthreads();
            #pragma unroll
            for (int kk = 0; kk < 16; kk += 4) {
                uint32_t x0[4], x1[4], y0[4], y1[4];
                #pragma unroll
                for (int u = 0; u < 4; u++) {
                    x0[u] = sX2[2 * ty][kk + u];
                    x1[u] = sX2[2 * ty + 1][kk + u];
                    y0[u] = sY2[2 * tx][kk + u];
                    y1[u] = sY2[2 * tx + 1][kk + u];
                }
                a00 += h2sum(hadd2(hadd2(htanh2(hmul2(x0[0], y0[0])), htanh2(hmul2(x0[1], y0[1]))),
                                   hadd2(htanh2(hmul2(x0[2], y0[2])), htanh2(hmul2(x0[3], y0[3])))));
                a01 += h2sum(hadd2(hadd2(htanh2(hmul2(x0[0], y1[0])), htanh2(hmul2(x0[1], y1[1]))),
                                   hadd2(htanh2(hmul2(x0[2], y1[2])), htanh2(hmul2(x0[3], y1[3])))));
                a10 += h2sum(hadd2(hadd2(htanh2(hmul2(x1[0], y0[0])), htanh2(hmul2(x1[1], y0[1]))),
                                   hadd2(htanh2(hmul2(x1[2], y0[2])), htanh2(hmul2(x1[3], y0[3])))));
                a11 += h2sum(hadd2(hadd2(htanh2(hmul2(x1[0], y1[0])), htanh2(hmul2(x1[1], y1[1]))),
                                   hadd2(htanh2(hmul2(x1[2], y1[2])), htanh2(hmul2(x1[3], y1[3])))));
            }
            __syncthreads();
        }

        // fused exp: |att| <= 27.7 -> exp <= 1.1e12, fp32-safe without max-shift
        const float e00 = __expf(a00 * INV_SQRT_H);
        const float e01 = __expf(a01 * INV_SQRT_H);
        const float e10 = __expf(a10 * INV_SQRT_H);
        const float e11 = __expf(a11 * INV_SQRT_H);

        const int i = bi + 2 * ty, j = bj + 2 * tx;
        g_E[i * NN + j]           = e00;
        g_E[i * NN + j + 1]       = e01;
        g_E[(i + 1) * NN + j]     = e10;
        g_E[(i + 1) * NN + j + 1] = e11;
        // scattered transpose store (sector traffic ~4.7MB, < 1us at LTS cap)
        g_ET[j * NN + i]           = e00;
        g_ET[(j + 1) * NN + i]     = e01;
        g_ET[j * NN + i + 1]       = e10;
        g_ET[(j + 1) * NN + i + 1] = e11;
    }
    grid_barrier();

    const int gw = blockIdx.x * 8 + wid;     // global warp id, 0..1151

    // ===== P1: inverse row/col sums of E (warp per row; coalesced) ==========
    if (gw < 2 * NN) {
        const float* row = (gw < NN) ? (g_E + gw * NN) : (g_ET + (gw - NN) * NN);
        float s = 0.f;
        #pragma unroll
        for (int l = 0; l < 12; l++) s += row[lane + 32 * l];
        s = warp_sum(s);
        if (lane == 0) {
            if (gw < NN) g_rinv[gw] = 1.0f / s;
            else         g_cinv[gw - NN] = 1.0f / s;
        }
    }
    grid_barrier();

    // ===== P2: typicalness factors (pre-scaled) ==============================
    if (gw < 2 * NN) {
        float s = 0.f;
        if (gw < NN) {
            const float* row = g_E + gw * NN;
            #pragma unroll
            for (int l = 0; l < 12; l++) {
                int m = lane + 32 * l;
                s += row[m] * g_cinv[m];
            }
            s = warp_sum(s);
            if (lane == 0) g_b[gw] = s * g_rinv[gw] * INV_N;
        } else {
            const int c = gw - NN;
            const float* row = g_ET + c * NN;
            #pragma unroll
            for (int l = 0; l < 12; l++) {
                int n = lane + 32 * l;
                s += row[n] * g_rinv[n];
            }
            s = warp_sum(s);
            if (lane == 0) g_a[c] = s * g_cinv[c] * INV_N;
        }
    }
    grid_barrier();

    // ===== P3: pooling weights ===============================================
    if (gw < 2 * NN) {
        float s = 0.f;
        if (gw < NN) {
            const float* row = g_E + gw * NN;
            #pragma unroll
            for (int l = 0; l < 12; l++) {
                int m = lane + 32 * l;
                s += row[m] * g_a[m];
            }
            s = warp_sum(s);
            if (lane == 0) g_w_hypo[gw] = s;
        } else {
            const int c = gw - NN;
            const float* row = g_ET + c * NN;
            #pragma unroll
            for (int l = 0; l < 12; l++) {
                int n = lane + 32 * l;
                s += row[n] * g_b[n];
            }
            s = warp_sum(s);
            if (lane == 0) g_w_hyper[c] = s;
        }
    }
    grid_barrier();

    // ===== P4: prototype partials ============================================
    if (blockIdx.x < 128) {
        const int mat = blockIdx.x >> 6;           // 0: Y/w_hyper, 1: X/w_hypo
        const int c = blockIdx.x & 63;
        const float* M  = mat ? X : Y;
        const float* wv = mat ? g_w_hypo : g_w_hyper;
        float* part     = mat ? g_xpart : g_hpart;
        const int r0 = c * 6;
        float acc0 = 0.f, acc1 = 0.f, acc2 = 0.f;
        #pragma unroll
        for (int r = 0; r < 6; r++) {
            const float wr = wv[r0 + r];
            const float* mp = M + (size_t)(r0 + r) * HH;
            acc0 += wr * mp[tid];
            acc1 += wr * mp[tid + 256];
            acc2 += wr * mp[tid + 512];
        }
        part[c * HH + tid]       = acc0;
        part[c * HH + tid + 256] = acc1;
        part[c * HH + tid + 512] = acc2;
    }
    grid_barrier();

    // ===== P5: combine partials -> prototypes ================================
    {
        const int g = blockIdx.x * 256 + tid;
        if (g < 2 * HH) {
            const int mat = (g >= HH);
            const int d = g - mat * HH;
            const float* part = mat ? g_xpart : g_hpart;
            float s = 0.f;
            #pragma unroll 8
            for (int c = 0; c < 64; c++) s += part[c * HH + d];
            if (mat) g_xp[d] = s;
            else     g_hp[d] = s;
        }
    }
    grid_barrier();

    // ===== P6: feats + classifier (block 0) ==================================
    if (blockIdx.x == 0) {
        __shared__ float sh[24];
        float p0 = 0.f, p1 = 0.f, p2 = 0.f;
        #pragma unroll
        for (int d = tid; d < HH; d += 256) {
            float hp = g_hp[d], xp = g_xp[d];
            float fd = hp - xp;
            float fm = hp * xp;
            p0 += W[d] * hp + W[HH + d] * xp + W[2 * HH + d] * fd + W[3 * HH + d] * fm;
            p1 += W[4 * HH + d] * hp + W[5 * HH + d] * xp + W[6 * HH + d] * fd + W[7 * HH + d] * fm;
            p2 += W[8 * HH + d] * hp + W[9 * HH + d] * xp + W[10 * HH + d] * fd + W[11 * HH + d] * fm;
        }
        p0 = warp_sum(p0); p1 = warp_sum(p1); p2 = warp_sum(p2);
        if (lane == 0) { sh[wid] = p0; sh[8 + wid] = p1; sh[16 + wid] = p2; }
        __syncthreads();
        if (tid == 0) {
            float s0 = 0.f, s1 = 0.f, s2 = 0.f;
            #pragma unroll
            for (int i = 0; i < 8; i++) { s0 += sh[i]; s1 += sh[8 + i]; s2 += sh[16 + i]; }
            out[0] = s0 + B[0];
            out[1] = s1 + B[1];
            out[2] = s2 + B[2];
        }
    }
}

// ---------------- launch ------------------------------------------------------
extern "C" void kernel_launch(void* const* d_in, const int* in_sizes, int n_in,
                              void* d_out, int out_size) {
    const float* X = (const float*)d_in[0];  // hypo_embeddings [384,768]
    const float* Y = (const float*)d_in[1];  // hyper_embeddings [384,768]
    const float* W = (const float*)d_in[2];  // W_cls [3,3072]
    const float* B = (const float*)d_in[3];  // b_cls [3]
    float* out = (float*)d_out;              // [3]

    fused_kernel<<<NB, 256>>>(X, Y, W, B, out);
}

// round 5
// speedup vs baseline: 1.0212x; 1.0212x over previous
#include <cuda_runtime.h>
#include <cstdint>

#define NN 384
#define HH 768
#define NB 576                              // 4 blocks/SM on 144 SMs; <=592 co-resident
#define INV_SQRT_H 0.03608439182435161f     // 1/sqrt(768)
#define INV_N      0.0026041666666666665f   // 1/384

// ---------------- scratch (device globals; no allocation allowed) ----------
__device__ float g_P [4 * NN * NN];         // k-split tanh-sum partials   2.25 MB
__device__ float g_E [NN * NN];             // exp(att)                    576 KB
__device__ float g_ET[NN * NN];             // exp(att) transposed         576 KB
__device__ float g_rinv[NN], g_cinv[NN];
__device__ float g_a[NN], g_b[NN];
__device__ float g_w_hypo[NN], g_w_hyper[NN];
__device__ float g_hpart[64 * HH], g_xpart[64 * HH];
__device__ float g_hp[HH], g_xp[HH];
__device__ unsigned g_arrive;               // monotonic barrier counter (replay-safe)

// ---------------- f16x2 helpers ----------------
__device__ __forceinline__ uint32_t packh2(float a, float b) {
    uint32_t d;
    asm("cvt.rn.f16x2.f32 %0, %1, %2;" : "=r"(d) : "f"(b), "f"(a));
    return d;
}
__device__ __forceinline__ uint32_t hmul2(uint32_t a, uint32_t b) {
    uint32_t d;
    asm("mul.rn.f16x2 %0, %1, %2;" : "=r"(d) : "r"(a), "r"(b));
    return d;
}
__device__ __forceinline__ uint32_t hadd2(uint32_t a, uint32_t b) {
    uint32_t d;
    asm("add.rn.f16x2 %0, %1, %2;" : "=r"(d) : "r"(a), "r"(b));
    return d;
}
__device__ __forceinline__ uint32_t htanh2(uint32_t a) {
    uint32_t d;
    asm("tanh.approx.f16x2 %0, %1;" : "=r"(d) : "r"(a));
    return d;
}
__device__ __forceinline__ float h2sum(uint32_t s) {
    float lo, hi;
    asm("{ .reg .b16 l, h;\n\t"
        "  mov.b32 {l, h}, %2;\n\t"
        "  cvt.f32.f16 %0, l;\n\t"
        "  cvt.f32.f16 %1, h; }"
        : "=f"(lo), "=f"(hi) : "r"(s));
    return lo + hi;
}

__device__ __forceinline__ float warp_sum(float v) {
    #pragma unroll
    for (int o = 16; o; o >>= 1) v += __shfl_xor_sync(0xffffffffu, v, o);
    return v;
}

// Software grid barrier. Monotonic counter -> safe across CUDA-graph replays.
// All NB blocks co-resident (4/SM enforced via __launch_bounds__), so no deadlock.
__device__ __forceinline__ void grid_barrier() {
    __syncthreads();
    __threadfence();
    if (threadIdx.x == 0) {
        unsigned my = atomicAdd(&g_arrive, 1u) + 1u;
        unsigned target = ((my + NB - 1u) / NB) * NB;
        unsigned cur;
        do {
            asm volatile("ld.global.acquire.gpu.b32 %0, [%1];"
                         : "=r"(cur) : "l"(&g_arrive));
        } while ((int)(cur - target) < 0);
    }
    __syncthreads();
    __threadfence();
}

// ---------------- single fused kernel ----------------------------------------
__global__ __launch_bounds__(256, 4) void fused_kernel(const float* __restrict__ X,
                                                       const float* __restrict__ Y,
                                                       const float* __restrict__ W,
                                                       const float* __restrict__ B,
                                                       float* __restrict__ out) {
    __shared__ uint32_t sX2[32][17];   // f16x2-packed tiles (k-pairs)
    __shared__ uint32_t sY2[32][17];

    const int tid = threadIdx.x;
    const int lane = tid & 31;
    const int wid = tid >> 5;

    // ===== Phase 0: k-split partials of sum_h tanh(X[n,h]*Y[m,h]) ===========
    // 576 blocks = 144 tiles (32x32) x 4 k-chunks of 192. 16x16 threads, 2x2 micro.
    {
        const int tile = blockIdx.x % 144;
        const int kc   = blockIdx.x / 144;       // 0..3
        const int tx = tid & 15;
        const int ty = tid >> 4;
        const int bi = (tile / 12) * 32;         // hypo rows
        const int bj = (tile % 12) * 32;         // hyper rows
        const int lr = tid >> 3;                 // 0..31 load row
        const int lf = (tid & 7) << 2;           // float offset 0..28
        const int lh = (tid & 7) << 1;           // half2 offset 0..14

        float a00 = 0.f, a01 = 0.f, a10 = 0.f, a11 = 0.f;

        const int kbeg = kc * 192, kend = kbeg + 192;
        for (int k0 = kbeg; k0 < kend; k0 += 32) {
            float4 vx = *(const float4*)(X + (size_t)(bi + lr) * HH + k0 + lf);
            float4 vy = *(const float4*)(Y + (size_t)(bj + lr) * HH + k0 + lf);
            sX2[lr][lh]     = packh2(vx.x, vx.y);
            sX2[lr][lh + 1] = packh2(vx.z, vx.w);
            sY2[lr][lh]     = packh2(vy.x, vy.y);
            sY2[lr][lh + 1] = packh2(vy.z, vy.w);
            __syncthreads();
            #pragma unroll
            for (int kk = 0; kk < 16; kk += 4) {
                uint32_t x0[4], x1[4], y0[4], y1[4];
                #pragma unroll
                for (int u = 0; u < 4; u++) {
                    x0[u] = sX2[2 * ty][kk + u];
                    x1[u] = sX2[2 * ty + 1][kk + u];
                    y0[u] = sY2[2 * tx][kk + u];
                    y1[u] = sY2[2 * tx + 1][kk + u];
                }
                a00 += h2sum(hadd2(hadd2(htanh2(hmul2(x0[0], y0[0])), htanh2(hmul2(x0[1], y0[1]))),
                                   hadd2(htanh2(hmul2(x0[2], y0[2])), htanh2(hmul2(x0[3], y0[3])))));
                a01 += h2sum(hadd2(hadd2(htanh2(hmul2(x0[0], y1[0])), htanh2(hmul2(x0[1], y1[1]))),
                                   hadd2(htanh2(hmul2(x0[2], y1[2])), htanh2(hmul2(x0[3], y1[3])))));
                a10 += h2sum(hadd2(hadd2(htanh2(hmul2(x1[0], y0[0])), htanh2(hmul2(x1[1], y0[1]))),
                                   hadd2(htanh2(hmul2(x1[2], y0[2])), htanh2(hmul2(x1[3], y0[3])))));
                a11 += h2sum(hadd2(hadd2(htanh2(hmul2(x1[0], y1[0])), htanh2(hmul2(x1[1], y1[1]))),
                                   hadd2(htanh2(hmul2(x1[2], y1[2])), htanh2(hmul2(x1[3], y1[3])))));
            }
            __syncthreads();
        }

        float* P = g_P + (size_t)kc * NN * NN;
        const int i = bi + 2 * ty, j = bj + 2 * tx;
        P[i * NN + j]           = a00;
        P[i * NN + j + 1]       = a01;
        P[(i + 1) * NN + j]     = a10;
        P[(i + 1) * NN + j + 1] = a11;
    }
    grid_barrier();

    // ===== Phase 0.5: combine k-partials -> E = exp(att), plus transpose ====
    {
        const int idx = blockIdx.x * 256 + tid;      // exactly covers 384*384
        float s = g_P[idx] + g_P[NN * NN + idx] + g_P[2 * NN * NN + idx] + g_P[3 * NN * NN + idx];
        float e = __expf(s * INV_SQRT_H);            // |att|<=27.7 -> fp32-safe
        g_E[idx] = e;
        const int i = idx / NN, j = idx - (idx / NN) * NN;
        g_ET[j * NN + i] = e;
    }
    grid_barrier();

    const int gw = blockIdx.x * 8 + wid;     // global warp id

    // ===== P1: inverse row/col sums of E (warp per row; coalesced) ==========
    if (gw < 2 * NN) {
        const float* row = (gw < NN) ? (g_E + gw * NN) : (g_ET + (gw - NN) * NN);
        float s = 0.f;
        #pragma unroll
        for (int l = 0; l < 12; l++) s += row[lane + 32 * l];
        s = warp_sum(s);
        if (lane == 0) {
            if (gw < NN) g_rinv[gw] = 1.0f / s;
            else         g_cinv[gw - NN] = 1.0f / s;
        }
    }
    grid_barrier();

    // ===== P2: typicalness factors (pre-scaled) ==============================
    if (gw < 2 * NN) {
        float s = 0.f;
        if (gw < NN) {
            const float* row = g_E + gw * NN;
            #pragma unroll
            for (int l = 0; l < 12; l++) {
                int m = lane + 32 * l;
                s += row[m] * g_cinv[m];
            }
            s = warp_sum(s);
            if (lane == 0) g_b[gw] = s * g_rinv[gw] * INV_N;
        } else {
            const int c = gw - NN;
            const float* row = g_ET + c * NN;
            #pragma unroll
            for (int l = 0; l < 12; l++) {
                int n = lane + 32 * l;
                s += row[n] * g_rinv[n];
            }
            s = warp_sum(s);
            if (lane == 0) g_a[c] = s * g_cinv[c] * INV_N;
        }
    }
    grid_barrier();

    // ===== P3: pooling weights ===============================================
    if (gw < 2 * NN) {
        float s = 0.f;
        if (gw < NN) {
            const float* row = g_E + gw * NN;
            #pragma unroll
            for (int l = 0; l < 12; l++) {
                int m = lane + 32 * l;
                s += row[m] * g_a[m];
            }
            s = warp_sum(s);
            if (lane == 0) g_w_hypo[gw] = s;
        } else {
            const int c = gw - NN;
            const float* row = g_ET + c * NN;
            #pragma unroll
            for (int l = 0; l < 12; l++) {
                int n = lane + 32 * l;
                s += row[n] * g_b[n];
            }
            s = warp_sum(s);
            if (lane == 0) g_w_hyper[c] = s;
        }
    }
    grid_barrier();

    // ===== P4: prototype partials ============================================
    if (blockIdx.x < 128) {
        const int mat = blockIdx.x >> 6;           // 0: Y/w_hyper, 1: X/w_hypo
        const int c = blockIdx.x & 63;
        const float* M  = mat ? X : Y;
        const float* wv = mat ? g_w_hypo : g_w_hyper;
        float* part     = mat ? g_xpart : g_hpart;
        const int r0 = c * 6;
        float acc0 = 0.f, acc1 = 0.f, acc2 = 0.f;
        #pragma unroll
        for (int r = 0; r < 6; r++) {
            const float wr = wv[r0 + r];
            const float* mp = M + (size_t)(r0 + r) * HH;
            acc0 += wr * mp[tid];
            acc1 += wr * mp[tid + 256];
            acc2 += wr * mp[tid + 512];
        }
        part[c * HH + tid]       = acc0;
        part[c * HH + tid + 256] = acc1;
        part[c * HH + tid + 512] = acc2;
    }
    grid_barrier();

    // ===== P5: combine partials -> prototypes ================================
    {
        const int g = blockIdx.x * 256 + tid;
        if (g < 2 * HH) {
            const int mat = (g >= HH);
            const int d = g - mat * HH;
            const float* part = mat ? g_xpart : g_hpart;
            float s = 0.f;
            #pragma unroll 8
            for (int c = 0; c < 64; c++) s += part[c * HH + d];
            if (mat) g_xp[d] = s;
            else     g_hp[d] = s;
        }
    }
    grid_barrier();

    // ===== P6: feats + classifier (block 0) ==================================
    if (blockIdx.x == 0) {
        __shared__ float sh[24];
        float p0 = 0.f, p1 = 0.f, p2 = 0.f;
        #pragma unroll
        for (int d = tid; d < HH; d += 256) {
            float hp = g_hp[d], xp = g_xp[d];
            float fd = hp - xp;
            float fm = hp * xp;
            p0 += W[d] * hp + W[HH + d] * xp + W[2 * HH + d] * fd + W[3 * HH + d] * fm;
            p1 += W[4 * HH + d] * hp + W[5 * HH + d] * xp + W[6 * HH + d] * fd + W[7 * HH + d] * fm;
            p2 += W[8 * HH + d] * hp + W[9 * HH + d] * xp + W[10 * HH + d] * fd + W[11 * HH + d] * fm;
        }
        p0 = warp_sum(p0); p1 = warp_sum(p1); p2 = warp_sum(p2);
        if (lane == 0) { sh[wid] = p0; sh[8 + wid] = p1; sh[16 + wid] = p2; }
        __syncthreads();
        if (tid == 0) {
            float s0 = 0.f, s1 = 0.f, s2 = 0.f;
            #pragma unroll
            for (int i = 0; i < 8; i++) { s0 += sh[i]; s1 += sh[8 + i]; s2 += sh[16 + i]; }
            out[0] = s0 + B[0];
            out[1] = s1 + B[1];
            out[2] = s2 + B[2];
        }
    }
}

// ---------------- launch ------------------------------------------------------
extern "C" void kernel_launch(void* const* d_in, const int* in_sizes, int n_in,
                              void* d_out, int out_size) {
    const float* X = (const float*)d_in[0];  // hypo_embeddings [384,768]
    const float* Y = (const float*)d_in[1];  // hyper_embeddings [384,768]
    const float* W = (const float*)d_in[2];  // W_cls [3,3072]
    const float* B = (const float*)d_in[3];  // b_cls [3]
    float* out = (float*)d_out;              // [3]

    fused_kernel<<<NB, 256>>>(X, Y, W, B, out);
}